// round 2
// baseline (speedup 1.0000x reference)
#include <cuda_runtime.h>
#include <math.h>

// Problem constants
#define DPROJ 8192      // projection dim
#define CIN   512       // input channels
#define HW    196       // 14*14 spatial positions
#define NB    32        // batch
#define KST   72        // padded i-stride (floats) for [k][i] smem tiles (72*4B = 288B, 16B aligned, 8-bank skew)

// Scratch (no cudaMalloc allowed) -----------------------------------------
__device__ int   g_h1[CIN], g_h2[CIN];
__device__ float g_s1[CIN], g_s2[CIN];
__device__ float g_Y[NB * DPROJ];

// -------------------------------------------------------------------------
// Extract count-sketch (h, s) from the dense sketch matrix: each row has
// exactly one nonzero (+-1).
__global__ void extract_kernel(const float* __restrict__ S, int which) {
    int row = blockIdx.x;
    const float* p = S + (size_t)row * DPROJ;
    int*   h = which ? g_h2 : g_h1;
    float* s = which ? g_s2 : g_s1;
    for (int c = threadIdx.x; c < DPROJ; c += blockDim.x) {
        float v = p[c];
        if (v != 0.0f) { h[row] = c; s[row] = v; }
    }
}

__global__ void zero_kernel() {
    int i = blockIdx.x * blockDim.x + threadIdx.x;
    if (i < NB * DPROJ) g_Y[i] = 0.0f;
}

// -------------------------------------------------------------------------
// Fused per-image Gram + count-sketch scatter.
// Grid: (8 i-tiles, 32 batches). Block: 256 threads.
// smem: s_xi [196][KST] (i-tile, transposed), s_xj [196][KST], s_y [8192].
extern __shared__ float smem[];
__global__ __launch_bounds__(256, 1) void gram_scatter_kernel(const float* __restrict__ x) {
    const int b  = blockIdx.y;
    const int it = blockIdx.x;
    float* s_xi = smem;                    // HW*KST floats
    float* s_xj = smem + HW * KST;         // HW*KST floats
    float* s_y  = smem + 2 * HW * KST;     // DPROJ floats
    const int tid = threadIdx.x;
    const float* xb = x + (size_t)b * CIN * HW;

    // zero smem accumulator
    for (int d0 = tid; d0 < DPROJ; d0 += 256) s_y[d0] = 0.0f;

    // load i-tile (channels it*64 .. it*64+63), transposed to [k][i]
    {
        const float* gsrc = xb + it * 64 * HW;
        for (int idx = tid; idx < 64 * HW; idx += 256) {
            int c = idx / HW, k = idx - c * HW;
            s_xi[k * KST + c] = gsrc[idx];
        }
    }

    const int ti = tid >> 4;    // 0..15 -> i-group of 4
    const int tj = tid & 15;    // 0..15 -> j-group of 4

    int   hi[4];
    float si[4];
    #pragma unroll
    for (int u = 0; u < 4; u++) {
        int gidx = it * 64 + ti * 4 + u;
        hi[u] = g_h1[gidx];
        si[u] = g_s1[gidx];
    }
    __syncthreads();

    for (int jt = 0; jt < 8; jt++) {
        // load j-tile, transposed
        {
            const float* gsrc = xb + jt * 64 * HW;
            for (int idx = tid; idx < 64 * HW; idx += 256) {
                int c = idx / HW, k = idx - c * HW;
                s_xj[k * KST + c] = gsrc[idx];
            }
        }
        __syncthreads();

        float acc00=0.f, acc01=0.f, acc02=0.f, acc03=0.f;
        float acc10=0.f, acc11=0.f, acc12=0.f, acc13=0.f;
        float acc20=0.f, acc21=0.f, acc22=0.f, acc23=0.f;
        float acc30=0.f, acc31=0.f, acc32=0.f, acc33=0.f;

        const float4* a4 = reinterpret_cast<const float4*>(s_xi);
        const float4* b4 = reinterpret_cast<const float4*>(s_xj);
        #pragma unroll 4
        for (int k = 0; k < HW; k++) {
            float4 a = a4[k * (KST / 4) + ti];
            float4 b = b4[k * (KST / 4) + tj];
            acc00 += a.x * b.x; acc01 += a.x * b.y; acc02 += a.x * b.z; acc03 += a.x * b.w;
            acc10 += a.y * b.x; acc11 += a.y * b.y; acc12 += a.y * b.z; acc13 += a.y * b.w;
            acc20 += a.z * b.x; acc21 += a.z * b.y; acc22 += a.z * b.z; acc23 += a.z * b.w;
            acc30 += a.w * b.x; acc31 += a.w * b.y; acc32 += a.w * b.z; acc33 += a.w * b.w;
        }

        float accm[4][4] = {
            {acc00, acc01, acc02, acc03},
            {acc10, acc11, acc12, acc13},
            {acc20, acc21, acc22, acc23},
            {acc30, acc31, acc32, acc33},
        };

        // scatter: y[(h1[i]+h2[j]) mod D] += s1[i]*s2[j]*G[i][j]
        #pragma unroll
        for (int v = 0; v < 4; v++) {
            int gj = jt * 64 + tj * 4 + v;
            int   h2v = g_h2[gj];
            float s2v = g_s2[gj];
            #pragma unroll
            for (int u = 0; u < 4; u++) {
                int dst = hi[u] + h2v;
                if (dst >= DPROJ) dst -= DPROJ;
                atomicAdd(&s_y[dst], accm[u][v] * (si[u] * s2v));
            }
        }
        __syncthreads();   // protect s_xj reuse + order scatter before flush
    }

    // flush per-CTA partial into global accumulator
    for (int d0 = tid; d0 < DPROJ; d0 += 256)
        atomicAdd(&g_Y[b * DPROJ + d0], s_y[d0]);
}

// -------------------------------------------------------------------------
// signed sqrt + L2 normalize per image
__global__ void finalize_kernel(float* __restrict__ out) {
    const int b = blockIdx.x, tid = threadIdx.x;
    float v[DPROJ / 256];
    float ss = 0.f;
    #pragma unroll
    for (int m = 0; m < DPROJ / 256; m++) {
        float y = g_Y[b * DPROJ + m * 256 + tid];
        float sv;
        if (y > 0.f)      sv =  sqrtf(y + 1e-8f);
        else if (y < 0.f) sv = -sqrtf(-y + 1e-8f);
        else              sv = 0.f;
        v[m] = sv;
        ss += sv * sv;
    }
    #pragma unroll
    for (int o = 16; o > 0; o >>= 1) ss += __shfl_xor_sync(0xffffffffu, ss, o);
    __shared__ float wsum[8];
    __shared__ float total;
    if ((tid & 31) == 0) wsum[tid >> 5] = ss;
    __syncthreads();
    if (tid == 0) {
        float t = 0.f;
        #pragma unroll
        for (int w = 0; w < 8; w++) t += wsum[w];
        total = t;
    }
    __syncthreads();
    float inv = 1.0f / fmaxf(sqrtf(total), 1e-12f);
    #pragma unroll
    for (int m = 0; m < DPROJ / 256; m++)
        out[b * DPROJ + m * 256 + tid] = v[m] * inv;
}

// -------------------------------------------------------------------------
extern "C" void kernel_launch(void* const* d_in, const int* in_sizes, int n_in,
                              void* d_out, int out_size) {
    (void)in_sizes; (void)n_in; (void)out_size;
    const float* x  = (const float*)d_in[0];
    const float* S1 = (const float*)d_in[1];
    const float* S2 = (const float*)d_in[2];
    float* out = (float*)d_out;

    const size_t smem_bytes = (size_t)(2 * HW * KST + DPROJ) * sizeof(float); // 145664 B
    cudaFuncSetAttribute(gram_scatter_kernel,
                         cudaFuncAttributeMaxDynamicSharedMemorySize,
                         (int)smem_bytes);

    extract_kernel<<<CIN, 256>>>(S1, 0);
    extract_kernel<<<CIN, 256>>>(S2, 1);
    zero_kernel<<<(NB * DPROJ + 1023) / 1024, 1024>>>();

    dim3 grid(8, NB);
    gram_scatter_kernel<<<grid, 256, smem_bytes>>>(x);

    finalize_kernel<<<NB, 256>>>(out);
}

// round 8
// speedup vs baseline: 1.4327x; 1.4327x over previous
#include <cuda_runtime.h>
#include <math.h>

#define DPROJ 8192      // projection dim (power of 2 -> mod via mask)
#define CIN   512
#define HW    196       // 14*14
#define NB    32
#define BC    128       // channel block
#define KCH   98        // k-chunk (2 chunks cover HW=196)
#define NPAIR 10        // symmetric block pairs I<=J of 512/128=4 blocks

// Scratch (no cudaMalloc allowed)
__device__ int   g_h1[CIN], g_h2[CIN];
__device__ float g_s1[CIN], g_s2[CIN];
__device__ float g_Y[NB * DPROJ];

__constant__ int c_I[NPAIR] = {0,0,0,0,1,1,1,2,2,3};
__constant__ int c_J[NPAIR] = {0,1,2,3,1,2,3,2,3,3};

// ---------------------------------------------------------------------------
__global__ void extract_kernel(const float* __restrict__ S, int which) {
    int row = blockIdx.x;
    const float* p = S + (size_t)row * DPROJ;
    int*   h = which ? g_h2 : g_h1;
    float* s = which ? g_s2 : g_s1;
    for (int c = threadIdx.x; c < DPROJ; c += blockDim.x) {
        float v = p[c];
        if (v != 0.0f) { h[row] = c; s[row] = v; }
    }
}

__global__ void zero_kernel() {
    int i = blockIdx.x * blockDim.x + threadIdx.x;
    if (i < NB * DPROJ) g_Y[i] = 0.0f;
}

// ---------------------------------------------------------------------------
// Transposed, XOR-swizzled tile load: dst logical [k][c] (KCH x BC floats).
// phys float index = k*BC + 4*((c>>2) ^ ((k>>1)&31)) + (c&3)
// -> STS conflict-free (fixed c, consecutive even k hit distinct banks)
// -> compute float4 LDS conflict-free (all lanes share k; bijection in c4)
__device__ __forceinline__ void load_tile(float* __restrict__ dst,
                                          const float* __restrict__ src,
                                          int kbase, int tid) {
    #pragma unroll 4
    for (int idx = tid; idx < BC * (KCH / 2); idx += 256) {
        int c  = idx / (KCH / 2);
        int k  = (idx - c * (KCH / 2)) * 2;
        float2 v = *reinterpret_cast<const float2*>(src + c * HW + kbase + k);
        int c4 = c >> 2, cl = c & 3;
        int sw = (k >> 1) & 31;                 // same for k and k+1
        int pc = ((c4 ^ sw) << 2) + cl;
        dst[(k    ) * BC + pc] = v.x;
        dst[(k + 1) * BC + pc] = v.y;
    }
}

// ---------------------------------------------------------------------------
// Fused symmetric-block Gram + count-sketch scatter (REDG to global).
// Grid: (10 pairs, 32 batches), 256 threads, 8x8 micro-tile -> 128x128 block.
extern __shared__ float sm[];
__global__ __launch_bounds__(256, 2) void gram_scatter_kernel(const float* __restrict__ x) {
    const int p = blockIdx.x, b = blockIdx.y;
    const int I = c_I[p], J = c_J[p];
    float* sA = sm;
    float* sB = (I == J) ? sm : sm + KCH * BC;
    const int tid = threadIdx.x;
    const int ti = tid >> 4, tj = tid & 15;
    const float* xb = x + (size_t)b * CIN * HW;

    float acc[8][8];
    #pragma unroll
    for (int u = 0; u < 8; u++)
        #pragma unroll
        for (int v = 0; v < 8; v++) acc[u][v] = 0.0f;

    for (int kc = 0; kc < 2; kc++) {
        if (kc) __syncthreads();
        load_tile(sA, xb + (size_t)I * BC * HW, kc * KCH, tid);
        if (J != I) load_tile(sB, xb + (size_t)J * BC * HW, kc * KCH, tid);
        __syncthreads();

        const float4* A4 = reinterpret_cast<const float4*>(sA);
        const float4* B4 = reinterpret_cast<const float4*>(sB);
        #pragma unroll 2
        for (int k = 0; k < KCH; k++) {
            const int sw = (k >> 1) & 31;
            const int rb = k * (BC / 4);
            float4 a0 = A4[rb + ((ti * 2    ) ^ sw)];
            float4 a1 = A4[rb + ((ti * 2 + 1) ^ sw)];
            float4 b0 = B4[rb + ((tj * 2    ) ^ sw)];
            float4 b1 = B4[rb + ((tj * 2 + 1) ^ sw)];
            float ar[8] = {a0.x,a0.y,a0.z,a0.w,a1.x,a1.y,a1.z,a1.w};
            float br[8] = {b0.x,b0.y,b0.z,b0.w,b1.x,b1.y,b1.z,b1.w};
            #pragma unroll
            for (int u = 0; u < 8; u++)
                #pragma unroll
                for (int v = 0; v < 8; v++)
                    acc[u][v] += ar[u] * br[v];
        }
    }

    // ---- scatter: y[(h1[i]+h2[j]) & 8191] += s1[i]*s2[j]*G[i,j] ----
    const int ib = I * BC + ti * 8;
    const int jb = J * BC + tj * 8;
    float* Yb = g_Y + b * DPROJ;

    int   h1i[8], h2j[8];
    float s1i[8], s2j[8];
    #pragma unroll
    for (int u = 0; u < 8; u++) { h1i[u] = g_h1[ib + u]; s1i[u] = g_s1[ib + u]; }
    #pragma unroll
    for (int v = 0; v < 8; v++) { h2j[v] = g_h2[jb + v]; s2j[v] = g_s2[jb + v]; }

    #pragma unroll
    for (int u = 0; u < 8; u++)
        #pragma unroll
        for (int v = 0; v < 8; v++)
            atomicAdd(Yb + ((h1i[u] + h2j[v]) & (DPROJ - 1)),
                      acc[u][v] * (s1i[u] * s2j[v]));

    if (I != J) {   // mirror block (J,I): G[j,i] = G[i,j]
        int   h1j[8], h2i[8];
        float s1j[8], s2i[8];
        #pragma unroll
        for (int v = 0; v < 8; v++) { h1j[v] = g_h1[jb + v]; s1j[v] = g_s1[jb + v]; }
        #pragma unroll
        for (int u = 0; u < 8; u++) { h2i[u] = g_h2[ib + u]; s2i[u] = g_s2[ib + u]; }
        #pragma unroll
        for (int u = 0; u < 8; u++)
            #pragma unroll
            for (int v = 0; v < 8; v++)
                atomicAdd(Yb + ((h1j[v] + h2i[u]) & (DPROJ - 1)),
                          acc[u][v] * (s1j[v] * s2i[u]));
    }
}

// ---------------------------------------------------------------------------
// signed sqrt + L2 normalize per image
__global__ void finalize_kernel(float* __restrict__ out) {
    const int b = blockIdx.x, tid = threadIdx.x;
    float v[DPROJ / 256];
    float ss = 0.f;
    #pragma unroll
    for (int m = 0; m < DPROJ / 256; m++) {
        float y = g_Y[b * DPROJ + m * 256 + tid];
        float sv;
        if (y > 0.f)      sv =  sqrtf(y + 1e-8f);
        else if (y < 0.f) sv = -sqrtf(-y + 1e-8f);
        else              sv = 0.f;
        v[m] = sv;
        ss += sv * sv;
    }
    #pragma unroll
    for (int o = 16; o > 0; o >>= 1) ss += __shfl_xor_sync(0xffffffffu, ss, o);
    __shared__ float wsum[8];
    __shared__ float total;
    if ((tid & 31) == 0) wsum[tid >> 5] = ss;
    __syncthreads();
    if (tid == 0) {
        float t = 0.f;
        #pragma unroll
        for (int w = 0; w < 8; w++) t += wsum[w];
        total = t;
    }
    __syncthreads();
    float inv = 1.0f / fmaxf(sqrtf(total), 1e-12f);
    #pragma unroll
    for (int m = 0; m < DPROJ / 256; m++)
        out[b * DPROJ + m * 256 + tid] = v[m] * inv;
}

// ---------------------------------------------------------------------------
extern "C" void kernel_launch(void* const* d_in, const int* in_sizes, int n_in,
                              void* d_out, int out_size) {
    (void)in_sizes; (void)n_in; (void)out_size;
    const float* x  = (const float*)d_in[0];
    const float* S1 = (const float*)d_in[1];
    const float* S2 = (const float*)d_in[2];
    float* out = (float*)d_out;

    const size_t smem_bytes = (size_t)(2 * KCH * BC) * sizeof(float); // 100352 B
    cudaFuncSetAttribute(gram_scatter_kernel,
                         cudaFuncAttributeMaxDynamicSharedMemorySize,
                         (int)smem_bytes);

    extract_kernel<<<CIN, 256>>>(S1, 0);
    extract_kernel<<<CIN, 256>>>(S2, 1);
    zero_kernel<<<(NB * DPROJ + 1023) / 1024, 1024>>>();

    dim3 grid(NPAIR, NB);
    gram_scatter_kernel<<<grid, 256, smem_bytes>>>(x);

    finalize_kernel<<<NB, 256>>>(out);
}

// round 9
// speedup vs baseline: 1.6020x; 1.1182x over previous
#include <cuda_runtime.h>
#include <math.h>

#define DPROJ 8192
#define CIN   512
#define HW    196
#define NB    32
#define BC    128
#define KCH   98
#define NPAIR 10

typedef unsigned long long u64;

// Scratch (no cudaMalloc allowed)
__device__ int   g_h1[CIN], g_h2[CIN];
__device__ float g_s1[CIN], g_s2[CIN];
__device__ float g_Y[NB * DPROJ];

__constant__ int c_I[NPAIR] = {0,0,0,0,1,1,1,2,2,3};
__constant__ int c_J[NPAIR] = {0,1,2,3,1,2,3,2,3,3};

// ---------------------------------------------------------------------------
// f32x2 helpers (sm_103a packed fp32 pipe; IEEE fp32 per lane)
__device__ __forceinline__ u64 pack2(float x) {
    u64 r; asm("mov.b64 %0, {%1, %1};" : "=l"(r) : "f"(x)); return r;
}
__device__ __forceinline__ void fma2(u64& acc, u64 a, u64 b) {
    asm("fma.rn.f32x2 %0, %1, %2, %0;" : "+l"(acc) : "l"(a), "l"(b));
}
__device__ __forceinline__ float2 unpack2(u64 v) {
    float2 r; asm("mov.b64 {%0, %1}, %2;" : "=f"(r.x), "=f"(r.y) : "l"(v)); return r;
}

// ---------------------------------------------------------------------------
// Fused prep: extract count-sketch (h,s) from S1/S2 rows + zero g_Y.
// Blocks [0,512): S1 rows; [512,1024): S2 rows; [1024,1280): zero Y (float4).
__global__ void prep_kernel(const float* __restrict__ S1,
                            const float* __restrict__ S2) {
    int blk = blockIdx.x;
    if (blk < 2 * CIN) {
        int which = blk >= CIN;
        int row = which ? blk - CIN : blk;
        const float* p = (which ? S2 : S1) + (size_t)row * DPROJ;
        int*   h = which ? g_h2 : g_h1;
        float* s = which ? g_s2 : g_s1;
        for (int c = threadIdx.x; c < DPROJ; c += blockDim.x) {
            float v = p[c];
            if (v != 0.0f) { h[row] = c; s[row] = v; }
        }
    } else {
        int i = (blk - 2 * CIN) * 256 + threadIdx.x;   // float4 index
        reinterpret_cast<float4*>(g_Y)[i] = make_float4(0.f, 0.f, 0.f, 0.f);
    }
}

// ---------------------------------------------------------------------------
// Transposed, XOR-swizzled tile load: dst logical [k][c] (KCH x BC floats).
// phys float index = k*BC + 4*((c>>2) ^ ((k>>1)&31)) + (c&3)
__device__ __forceinline__ void load_tile(float* __restrict__ dst,
                                          const float* __restrict__ src,
                                          int kbase, int tid) {
    #pragma unroll 4
    for (int idx = tid; idx < BC * (KCH / 2); idx += 256) {
        int c  = idx / (KCH / 2);
        int k  = (idx - c * (KCH / 2)) * 2;
        float2 v = *reinterpret_cast<const float2*>(src + c * HW + kbase + k);
        int c4 = c >> 2, cl = c & 3;
        int sw = (k >> 1) & 31;
        int pc = ((c4 ^ sw) << 2) + cl;
        dst[(k    ) * BC + pc] = v.x;
        dst[(k + 1) * BC + pc] = v.y;
    }
}

// ---------------------------------------------------------------------------
// Fused symmetric-block Gram + count-sketch scatter (REDG to global).
// Grid: (10 pairs, 32 batches), 256 threads, 8x8 micro-tile via f32x2 FMA.
extern __shared__ float sm[];
__global__ __launch_bounds__(256, 2) void gram_scatter_kernel(const float* __restrict__ x) {
    const int p = blockIdx.x, b = blockIdx.y;
    const int I = c_I[p], J = c_J[p];
    float* sA = sm;
    float* sB = (I == J) ? sm : sm + KCH * BC;
    const int tid = threadIdx.x;
    const int ti = tid >> 4, tj = tid & 15;
    const float* xb = x + (size_t)b * CIN * HW;

    u64 acc2[8][4];   // acc2[u][v2] = packed {G[u][2v2], G[u][2v2+1]}
    #pragma unroll
    for (int u = 0; u < 8; u++)
        #pragma unroll
        for (int v = 0; v < 4; v++) acc2[u][v] = 0ull;

    for (int kc = 0; kc < 2; kc++) {
        if (kc) __syncthreads();
        load_tile(sA, xb + (size_t)I * BC * HW, kc * KCH, tid);
        if (J != I) load_tile(sB, xb + (size_t)J * BC * HW, kc * KCH, tid);
        __syncthreads();

        const float4*     A4 = reinterpret_cast<const float4*>(sA);
        const ulonglong2* B2 = reinterpret_cast<const ulonglong2*>(sB);
        #pragma unroll 1
        for (int kk = 0; kk < KCH / 2; kk++) {
            const int sw  = kk & 31;
            const int rb  = (2 * kk) * (BC / 4);
            const int ia0 = (ti * 2) ^ sw;      // logical c4 = ti*2   (u=0..3)
            const int ia1 = ia0 ^ 1;            // logical c4 = ti*2+1 (u=4..7)
            const int ib0 = (tj * 2) ^ sw;      // logical v=0..3
            const int ib1 = ib0 ^ 1;            // logical v=4..7

            #pragma unroll
            for (int h = 0; h < 2; h++) {       // k = 2kk, 2kk+1
                const int r = rb + h * (BC / 4);
                float4     a0 = A4[r + ia0];
                float4     a1 = A4[r + ia1];
                ulonglong2 b0 = B2[r + ib0];
                ulonglong2 b1 = B2[r + ib1];
                float ar[8] = {a0.x,a0.y,a0.z,a0.w,a1.x,a1.y,a1.z,a1.w};
                #pragma unroll
                for (int u = 0; u < 8; u++) {
                    u64 ad = pack2(ar[u]);
                    fma2(acc2[u][0], ad, b0.x);
                    fma2(acc2[u][1], ad, b0.y);
                    fma2(acc2[u][2], ad, b1.x);
                    fma2(acc2[u][3], ad, b1.y);
                }
            }
        }
    }

    // ---- scatter: y[(h1[i]+h2[j]) & 8191] += s1[i]*s2[j]*G[i,j] ----
    const int ib = I * BC + ti * 8;
    const int jb = J * BC + tj * 8;
    float* Yb = g_Y + b * DPROJ;

    float accm[8][8];
    #pragma unroll
    for (int u = 0; u < 8; u++)
        #pragma unroll
        for (int v2 = 0; v2 < 4; v2++) {
            float2 t = unpack2(acc2[u][v2]);
            accm[u][2 * v2]     = t.x;
            accm[u][2 * v2 + 1] = t.y;
        }

    int   h1i[8], h2j[8];
    float s1i[8], s2j[8];
    #pragma unroll
    for (int u = 0; u < 8; u++) { h1i[u] = g_h1[ib + u]; s1i[u] = g_s1[ib + u]; }
    #pragma unroll
    for (int v = 0; v < 8; v++) { h2j[v] = g_h2[jb + v]; s2j[v] = g_s2[jb + v]; }

    #pragma unroll
    for (int u = 0; u < 8; u++)
        #pragma unroll
        for (int v = 0; v < 8; v++)
            atomicAdd(Yb + ((h1i[u] + h2j[v]) & (DPROJ - 1)),
                      accm[u][v] * (s1i[u] * s2j[v]));

    if (I != J) {   // mirror block (J,I): G[j,i] = G[i,j]
        int   h1j[8], h2i[8];
        float s1j[8], s2i[8];
        #pragma unroll
        for (int v = 0; v < 8; v++) { h1j[v] = g_h1[jb + v]; s1j[v] = g_s1[jb + v]; }
        #pragma unroll
        for (int u = 0; u < 8; u++) { h2i[u] = g_h2[ib + u]; s2i[u] = g_s2[ib + u]; }
        #pragma unroll
        for (int u = 0; u < 8; u++)
            #pragma unroll
            for (int v = 0; v < 8; v++)
                atomicAdd(Yb + ((h1j[v] + h2i[u]) & (DPROJ - 1)),
                          accm[u][v] * (s1j[v] * s2i[u]));
    }
}

// ---------------------------------------------------------------------------
// signed sqrt + L2 normalize per image
__global__ void finalize_kernel(float* __restrict__ out) {
    const int b = blockIdx.x, tid = threadIdx.x;
    float v[DPROJ / 256];
    float ss = 0.f;
    #pragma unroll
    for (int m = 0; m < DPROJ / 256; m++) {
        float y = g_Y[b * DPROJ + m * 256 + tid];
        float sv;
        if (y > 0.f)      sv =  sqrtf(y + 1e-8f);
        else if (y < 0.f) sv = -sqrtf(-y + 1e-8f);
        else              sv = 0.f;
        v[m] = sv;
        ss += sv * sv;
    }
    #pragma unroll
    for (int o = 16; o > 0; o >>= 1) ss += __shfl_xor_sync(0xffffffffu, ss, o);
    __shared__ float wsum[8];
    __shared__ float total;
    if ((tid & 31) == 0) wsum[tid >> 5] = ss;
    __syncthreads();
    if (tid == 0) {
        float t = 0.f;
        #pragma unroll
        for (int w = 0; w < 8; w++) t += wsum[w];
        total = t;
    }
    __syncthreads();
    float inv = 1.0f / fmaxf(sqrtf(total), 1e-12f);
    #pragma unroll
    for (int m = 0; m < DPROJ / 256; m++)
        out[b * DPROJ + m * 256 + tid] = v[m] * inv;
}

// ---------------------------------------------------------------------------
extern "C" void kernel_launch(void* const* d_in, const int* in_sizes, int n_in,
                              void* d_out, int out_size) {
    (void)in_sizes; (void)n_in; (void)out_size;
    const float* x  = (const float*)d_in[0];
    const float* S1 = (const float*)d_in[1];
    const float* S2 = (const float*)d_in[2];
    float* out = (float*)d_out;

    const size_t smem_bytes = (size_t)(2 * KCH * BC) * sizeof(float); // 100352 B
    cudaFuncSetAttribute(gram_scatter_kernel,
                         cudaFuncAttributeMaxDynamicSharedMemorySize,
                         (int)smem_bytes);

    // prep: 1024 extract blocks + 256 zero blocks (NB*DPROJ/1024 float4s each)
    prep_kernel<<<2 * CIN + (NB * DPROJ / 4) / 256, 256>>>(S1, S2);

    dim3 grid(NPAIR, NB);
    gram_scatter_kernel<<<grid, 256, smem_bytes>>>(x);

    finalize_kernel<<<NB, 256>>>(out);
}